// round 2
// baseline (speedup 1.0000x reference)
#include <cuda_runtime.h>
#include <cstdint>

// Problem constants (shapes fixed by the reference)
#define NF      128      // node/edge feature width; also OUT residual width
#define INDIM   384
#define HID     256
#define ODIM    128
#define BM      64       // edge rows per CTA
#define KC      32       // K chunk
#define NTH     256

// smem geometry (floats)
#define XS_W    132      // duplicated X row: 2*64 data + 4 pad
#define W1S_W   256
#define HS_W    512      // duplicated hidden row: 2*256
#define W2S_W   128

#define SMEM_BYTES (BM * HS_W * 4 + KC * W2S_W * 4)   // 147456 B (covers phase-1's 49664 B too)

// ---------------------------------------------------------------------------
// packed fp32x2 FMA (sm_100+): d = a*b + d elementwise on two fp32 lanes
// ---------------------------------------------------------------------------
__device__ __forceinline__ void ffma2(unsigned long long &d,
                                      unsigned long long a,
                                      unsigned long long b) {
    asm("fma.rn.f32x2 %0, %1, %2, %0;" : "+l"(d) : "l"(a), "l"(b));
}

__device__ __forceinline__ float2 u2f2(unsigned long long v) {
    float2 f;
    asm("mov.b64 {%0, %1}, %2;" : "=f"(f.x), "=f"(f.y) : "l"(v));
    return f;
}

// ---------------------------------------------------------------------------
// global->register chunk loaders (prefetch), register->smem stores
// ---------------------------------------------------------------------------
__device__ __forceinline__ void load_x(float xr[8], int c, int tid, int row0, int E,
                                       const float* __restrict__ src,
                                       const float* __restrict__ dst,
                                       const float* __restrict__ edge)
{
    const float* xp = (c < 4) ? src : ((c < 8) ? dst : edge);
    const int colbase = (c & 3) * KC;
#pragma unroll
    for (int i = 0; i < 8; i++) {
        int lin = tid + i * NTH;          // 0..2047 : 64 rows x 32 k
        int kk  = lin & 31;
        int r   = lin >> 5;
        int rg  = row0 + r;
        xr[i] = (rg < E) ? __ldg(xp + (size_t)rg * NF + colbase + kk) : 0.0f;
    }
}

__device__ __forceinline__ void store_x(const float xr[8], int tid, float* Xs2)
{
#pragma unroll
    for (int i = 0; i < 8; i++) {
        int lin = tid + i * NTH;
        int kk  = lin & 31;
        int r   = lin >> 5;
        // duplicated pair {x,x} -> single STS.64
        *reinterpret_cast<float2*>(&Xs2[kk * XS_W + 2 * r]) = make_float2(xr[i], xr[i]);
    }
}

__device__ __forceinline__ void load_w1(float wr[32], int c, int tid,
                                        const float* __restrict__ W1)
{
    const int k0 = c * KC;
#pragma unroll
    for (int i = 0; i < 32; i++) {
        int lin = tid + i * NTH;          // 0..8191 : 32 k x 256 cols
        int col = lin & 255;
        int kk  = lin >> 8;
        wr[i] = __ldg(W1 + (size_t)(k0 + kk) * HID + col);
    }
}

__device__ __forceinline__ void store_w1(const float wr[32], int tid, float* W1s)
{
#pragma unroll
    for (int i = 0; i < 32; i++) {
        int lin = tid + i * NTH;
        int col = lin & 255;
        int kk  = lin >> 8;
        W1s[kk * W1S_W + col] = wr[i];
    }
}

__device__ __forceinline__ void load_w2(float wr[16], int c, int tid,
                                        const float* __restrict__ W2)
{
    const int k0 = c * KC;
#pragma unroll
    for (int i = 0; i < 16; i++) {
        int lin = tid + i * NTH;          // 0..4095 : 32 k x 128 cols
        int col = lin & 127;
        int kk  = lin >> 7;
        wr[i] = __ldg(W2 + (size_t)(k0 + kk) * ODIM + col);
    }
}

__device__ __forceinline__ void store_w2(const float wr[16], int tid, float* W2s)
{
#pragma unroll
    for (int i = 0; i < 16; i++) {
        int lin = tid + i * NTH;
        int col = lin & 127;
        int kk  = lin >> 7;
        W2s[kk * W2S_W + col] = wr[i];
    }
}

// ---------------------------------------------------------------------------
// fused edge-MLP kernel
// out[e] = relu(concat(src,dst,edge)[e] @ W1 + b1) @ W2 + b2 + edge[e]
// ---------------------------------------------------------------------------
__global__ void __launch_bounds__(NTH, 1)
edge_mlp_kernel(const float* __restrict__ src,
                const float* __restrict__ dst,
                const float* __restrict__ edge,
                const float* __restrict__ W1,
                const float* __restrict__ b1,
                const float* __restrict__ W2,
                const float* __restrict__ b2,
                float* __restrict__ out,
                int E)
{
    extern __shared__ float sm[];
    float* Xs2 = sm;                      // phase1: [KC][XS_W]   (duplicated X)
    float* W1s = sm + KC * XS_W;          // phase1: [KC][W1S_W]
    float* Hs2 = sm;                      // phase2: [BM][HS_W]   (duplicated H)
    float* W2s = sm + BM * HS_W;          // phase2: [KC][W2S_W]

    const int tid  = threadIdx.x;
    const int tx   = tid & 31;            // col lane
    const int ty   = tid >> 5;            // row group (0..7), 8 rows each
    const int row0 = blockIdx.x * BM;

    // =================== phase 1: H = relu(X @ W1 + b1) ===================
    unsigned long long acc[8][4];
#pragma unroll
    for (int r = 0; r < 8; r++)
#pragma unroll
        for (int cc = 0; cc < 4; cc++) acc[r][cc] = 0ull;

    float xr[8];
    float wr[32];

    load_x(xr, 0, tid, row0, E, src, dst, edge);
    load_w1(wr, 0, tid, W1);
    store_x(xr, tid, Xs2);
    store_w1(wr, tid, W1s);

    for (int c = 0; c < 12; c++) {
        __syncthreads();                  // chunk c resident in smem
        if (c < 11) {                     // prefetch chunk c+1 while computing
            load_x(xr, c + 1, tid, row0, E, src, dst, edge);
            load_w1(wr, c + 1, tid, W1);
        }
#pragma unroll 8
        for (int kk = 0; kk < KC; kk++) {
            unsigned long long a[8];
#pragma unroll
            for (int r = 0; r < 8; r++)
                a[r] = *reinterpret_cast<const unsigned long long*>(
                           &Xs2[kk * XS_W + 2 * (ty * 8 + r)]);   // {x,x} broadcast
            unsigned long long b[4];
#pragma unroll
            for (int cc = 0; cc < 4; cc++)
                b[cc] = *reinterpret_cast<const unsigned long long*>(
                           &W1s[kk * W1S_W + tx * 2 + 64 * cc]);  // {w0,w1} pair
#pragma unroll
            for (int r = 0; r < 8; r++)
#pragma unroll
                for (int cc = 0; cc < 4; cc++)
                    ffma2(acc[r][cc], a[r], b[cc]);
        }
        __syncthreads();                  // everyone done reading chunk c
        if (c < 11) {
            store_x(xr, tid, Xs2);
            store_w1(wr, tid, W1s);
        }
    }

    // bias + relu, write duplicated H into smem (overwrites Xs2/W1s region)
    float2 b1v[4];
#pragma unroll
    for (int cc = 0; cc < 4; cc++)
        b1v[cc] = *reinterpret_cast<const float2*>(&b1[tx * 2 + 64 * cc]);

#pragma unroll
    for (int r = 0; r < 8; r++) {
        const int rr = ty * 8 + r;
#pragma unroll
        for (int cc = 0; cc < 4; cc++) {
            float2 v = u2f2(acc[r][cc]);
            v.x = fmaxf(v.x + b1v[cc].x, 0.0f);
            v.y = fmaxf(v.y + b1v[cc].y, 0.0f);
            // duplicated layout: {h0,h0,h1,h1} at 2*col — one STS.128
            *reinterpret_cast<float4*>(&Hs2[rr * HS_W + (tx * 2 + 64 * cc) * 2]) =
                make_float4(v.x, v.x, v.y, v.y);
        }
    }

    // =================== phase 2: OUT = H @ W2 + b2 + edge ===================
    unsigned long long acc2[8][2];
#pragma unroll
    for (int r = 0; r < 8; r++)
#pragma unroll
        for (int cc = 0; cc < 2; cc++) acc2[r][cc] = 0ull;

    float w2r[16];
    load_w2(w2r, 0, tid, W2);
    store_w2(w2r, tid, W2s);              // disjoint smem region; safe pre-sync

    for (int c = 0; c < 8; c++) {
        __syncthreads();                  // Hs2 + W2s chunk c visible
        if (c < 7) load_w2(w2r, c + 1, tid, W2);
#pragma unroll 4
        for (int kk = 0; kk < KC; kk++) {
            const int k = c * KC + kk;
            unsigned long long a[8];
#pragma unroll
            for (int r = 0; r < 8; r++)
                a[r] = *reinterpret_cast<const unsigned long long*>(
                           &Hs2[(ty * 8 + r) * HS_W + 2 * k]);    // {h,h} broadcast
            unsigned long long b[2];
#pragma unroll
            for (int cc = 0; cc < 2; cc++)
                b[cc] = *reinterpret_cast<const unsigned long long*>(
                           &W2s[kk * W2S_W + tx * 2 + 64 * cc]);
#pragma unroll
            for (int r = 0; r < 8; r++)
#pragma unroll
                for (int cc = 0; cc < 2; cc++)
                    ffma2(acc2[r][cc], a[r], b[cc]);
        }
        __syncthreads();
        if (c < 7) store_w2(w2r, tid, W2s);
    }

    // epilogue: + b2 + edge_attr residual, store
    float2 b2v[2];
#pragma unroll
    for (int cc = 0; cc < 2; cc++)
        b2v[cc] = *reinterpret_cast<const float2*>(&b2[tx * 2 + 64 * cc]);

#pragma unroll
    for (int r = 0; r < 8; r++) {
        const int rg = row0 + ty * 8 + r;
        if (rg < E) {
#pragma unroll
            for (int cc = 0; cc < 2; cc++) {
                const int col = tx * 2 + 64 * cc;
                float2 v  = u2f2(acc2[r][cc]);
                float2 ea = *reinterpret_cast<const float2*>(
                                &edge[(size_t)rg * NF + col]);
                v.x += b2v[cc].x + ea.x;
                v.y += b2v[cc].y + ea.y;
                *reinterpret_cast<float2*>(&out[(size_t)rg * ODIM + col]) = v;
            }
        }
    }
}

// ---------------------------------------------------------------------------
// launch: inputs per metadata order:
// 0=src 1=dest 2=edge_attr 3=u(unused) 4=batch(unused) 5=W1 6=b1 7=W2 8=b2
// ---------------------------------------------------------------------------
extern "C" void kernel_launch(void* const* d_in, const int* in_sizes, int n_in,
                              void* d_out, int out_size)
{
    const float* src  = (const float*)d_in[0];
    const float* dst  = (const float*)d_in[1];
    const float* edge = (const float*)d_in[2];
    const float* W1   = (const float*)d_in[5];
    const float* b1   = (const float*)d_in[6];
    const float* W2   = (const float*)d_in[7];
    const float* b2   = (const float*)d_in[8];
    float* out = (float*)d_out;

    const int E = in_sizes[0] / NF;

    cudaFuncSetAttribute(edge_mlp_kernel,
                         cudaFuncAttributeMaxDynamicSharedMemorySize, SMEM_BYTES);

    const int grid = (E + BM - 1) / BM;
    edge_mlp_kernel<<<grid, NTH, SMEM_BYTES>>>(src, dst, edge, W1, b1, W2, b2, out, E);
}

// round 5
// speedup vs baseline: 5.4802x; 5.4802x over previous
#include <cuda_runtime.h>
#include <cstdint>

#define NF   128
#define HID  256
#define NTH  512
#define BM   128

// smem geometry (float indices); pads chosen for conflict-free fragment LDS
#define AW   36            // A chunk row pitch   [128][36]
#define B1W  264           // W1 chunk row pitch  [32][264]
#define HW   260           // H row pitch         [128][260]
#define B2W  136           // W2 chunk row pitch  [32][136]

#define A_SZ   (128 * AW)      // 4608 floats per buffer
#define B1_SZ  (32 * B1W)      // 8448
#define H_SZ   (128 * HW)      // 33280
#define B2_SZ  (32 * B2W)      // 4352

#define OFF_A   0
#define OFF_B1  (OFF_A + 2 * A_SZ)     // 9216
#define OFF_H   0                       // phase2 overlays phase1 A/B1 region
#define OFF_B2  (OFF_H + H_SZ)          // 33280 (beyond phase1's 26112 -> disjoint)
#define SMEM_FLOATS (OFF_B2 + 2 * B2_SZ)   // 41984
#define SMEM_BYTES  (SMEM_FLOATS * 4)      // 167936

// ---------------------------------------------------------------------------
static __device__ __forceinline__ uint32_t s2u(const void* p){
    uint32_t a;
    asm("{ .reg .u64 t; cvta.to.shared.u64 t, %1; cvt.u32.u64 %0, t; }" : "=r"(a) : "l"(p));
    return a;
}
static __device__ __forceinline__ uint32_t tf32b(float f){
    uint32_t u; asm("cvt.rna.tf32.f32 %0, %1;" : "=r"(u) : "f"(f)); return u;
}
static __device__ __forceinline__ void cp16(uint32_t d, const void* g, uint32_t nbytes){
    asm volatile("cp.async.ca.shared.global [%0], [%1], 16, %2;"
                 :: "r"(d), "l"(g), "r"(nbytes) : "memory");
}
static __device__ __forceinline__ void cp_commit(){
    asm volatile("cp.async.commit_group;" ::: "memory");
}
static __device__ __forceinline__ void cp_wait1(){
    asm volatile("cp.async.wait_group 1;" ::: "memory");
}
static __device__ __forceinline__ void cp_wait0(){
    asm volatile("cp.async.wait_group 0;" ::: "memory");
}
// D += A*B, m16n8k8 tf32
static __device__ __forceinline__ void mma8(float* c, const uint32_t* a, const uint32_t* b){
    asm volatile("mma.sync.aligned.m16n8k8.row.col.f32.tf32.tf32.f32 "
        "{%0,%1,%2,%3}, {%4,%5,%6,%7}, {%8,%9}, {%0,%1,%2,%3};"
        : "+f"(c[0]), "+f"(c[1]), "+f"(c[2]), "+f"(c[3])
        : "r"(a[0]), "r"(a[1]), "r"(a[2]), "r"(a[3]), "r"(b[0]), "r"(b[1]));
}

// ---------------------------------------------------------------------------
// fused edge-MLP: out = relu([src,dst,edge] @ W1 + b1) @ W2 + b2 + edge
// ---------------------------------------------------------------------------
__global__ void __launch_bounds__(NTH, 1)
edge_mlp_mma(const float* __restrict__ src, const float* __restrict__ dst,
             const float* __restrict__ edg, const float* __restrict__ W1,
             const float* __restrict__ b1,  const float* __restrict__ W2,
             const float* __restrict__ b2,  float* __restrict__ out, int E)
{
    extern __shared__ float sm[];
    float* As  = sm + OFF_A;
    float* Bs  = sm + OFF_B1;
    float* Hs  = sm + OFF_H;
    float* B2s = sm + OFF_B2;

    const int tid  = threadIdx.x;
    const int lane = tid & 31, wid = tid >> 5;
    const int g = lane >> 2, t = lane & 3;       // groupID, threadID-in-group
    const int row0 = blockIdx.x * BM;

    // ---- async copy helpers ----
    auto copyA = [&](int c, int buf){
        const float* xp = (c < 4) ? src : (c < 8) ? dst : edg;
        const int cb = (c & 3) * 32;
        float* d = As + buf * A_SZ;
#pragma unroll
        for (int i = 0; i < 2; i++){
            int lin = tid + i * NTH;             // 0..1023
            int kq = lin & 7, r = lin >> 3;
            int rg = row0 + r;
            int rs = (rg < E) ? rg : (E - 1);    // clamp addr; zfill via nbytes=0
            cp16(s2u(d + r * AW + kq * 4),
                 xp + (size_t)rs * NF + cb + kq * 4, (rg < E) ? 16u : 0u);
        }
    };
    auto copyB1 = [&](int c, int buf){
        float* d = Bs + buf * B1_SZ;
#pragma unroll
        for (int i = 0; i < 4; i++){
            int lin = tid + i * NTH;             // 0..2047
            int n4 = lin & 63, k = lin >> 6;
            cp16(s2u(d + k * B1W + n4 * 4),
                 W1 + (size_t)(c * 32 + k) * HID + n4 * 4, 16u);
        }
    };
    auto copyB2 = [&](int c, int buf){
        float* d = B2s + buf * B2_SZ;
#pragma unroll
        for (int i = 0; i < 2; i++){
            int lin = tid + i * NTH;             // 0..1023
            int n4 = lin & 31, k = lin >> 5;
            cp16(s2u(d + k * B2W + n4 * 4),
                 W2 + (size_t)(c * 32 + k) * NF + n4 * 4, 16u);
        }
    };

    // =================== phase 1: D1 = X @ W1  (K = 384) ===================
    const int wm = wid & 1, wn = wid >> 1;       // 2 x 8 warp grid
    const int rb = wm * 64, nb = wn * 32;        // warp tile 64 x 32

    float acc[4][4][4];
#pragma unroll
    for (int ma = 0; ma < 4; ma++)
#pragma unroll
        for (int na = 0; na < 4; na++)
#pragma unroll
            for (int q = 0; q < 4; q++) acc[ma][na][q] = 0.f;

    copyA(0, 0); copyB1(0, 0); cp_commit();
    copyA(1, 1); copyB1(1, 1); cp_commit();

    for (int c = 0; c < 12; c++){
        const int buf = c & 1;
        if (c < 11) cp_wait1(); else cp_wait0();
        __syncthreads();
        const float* Ab = As + buf * A_SZ;
        const float* Bb = Bs + buf * B1_SZ;
#pragma unroll
        for (int kk = 0; kk < 4; kk++){
            uint32_t a[4][4], b[4][2];
#pragma unroll
            for (int ma = 0; ma < 4; ma++){
                const float* ap = Ab + (rb + ma * 16 + g) * AW + kk * 8 + t;
                a[ma][0] = tf32b(ap[0]);
                a[ma][1] = tf32b(ap[8 * AW]);
                a[ma][2] = tf32b(ap[4]);
                a[ma][3] = tf32b(ap[8 * AW + 4]);
            }
#pragma unroll
            for (int na = 0; na < 4; na++){
                const float* bp = Bb + (kk * 8 + t) * B1W + nb + na * 8 + g;
                b[na][0] = tf32b(bp[0]);
                b[na][1] = tf32b(bp[4 * B1W]);
            }
#pragma unroll
            for (int ma = 0; ma < 4; ma++)
#pragma unroll
                for (int na = 0; na < 4; na++)
                    mma8(acc[ma][na], a[ma], b[na]);
        }
        __syncthreads();
        if (c < 10){ copyA(c + 2, buf); copyB1(c + 2, buf); cp_commit(); }
    }

    // ======= epilogue 1: H = tf32(relu(D1 + b1)) -> smem (overlays A/B1) ====
    copyB2(0, 0); cp_commit();                   // overlap W2 c0 with epilogue

    uint32_t* Hu = reinterpret_cast<uint32_t*>(Hs);
#pragma unroll
    for (int na = 0; na < 4; na++){
        const int col = nb + na * 8 + 2 * t;
        const float2 bv = *reinterpret_cast<const float2*>(b1 + col);
#pragma unroll
        for (int ma = 0; ma < 4; ma++){
            const int r0 = rb + ma * 16 + g;
            float h0 = fmaxf(acc[ma][na][0] + bv.x, 0.f);
            float h1 = fmaxf(acc[ma][na][1] + bv.y, 0.f);
            float h2 = fmaxf(acc[ma][na][2] + bv.x, 0.f);
            float h3 = fmaxf(acc[ma][na][3] + bv.y, 0.f);
            *reinterpret_cast<uint2*>(&Hu[r0 * HW + col]) =
                make_uint2(tf32b(h0), tf32b(h1));
            *reinterpret_cast<uint2*>(&Hu[(r0 + 8) * HW + col]) =
                make_uint2(tf32b(h2), tf32b(h3));
        }
    }

    copyB2(1, 1); cp_commit();
    __syncthreads();                              // H visible to all warps

    // =================== phase 2: D2 = H @ W2  (K = 256) ===================
    const int wm2 = wid & 3, wn2 = wid >> 2;     // 4 x 4 warp grid
    const int rb2 = wm2 * 32, nb2 = wn2 * 32;    // warp tile 32 x 32

    float acc2[2][4][4];
#pragma unroll
    for (int ma = 0; ma < 2; ma++)
#pragma unroll
        for (int na = 0; na < 4; na++)
#pragma unroll
            for (int q = 0; q < 4; q++) acc2[ma][na][q] = 0.f;

    for (int c = 0; c < 8; c++){
        const int buf = c & 1;
        if (c < 7) cp_wait1(); else cp_wait0();
        __syncthreads();
        const float* Bb = B2s + buf * B2_SZ;
#pragma unroll
        for (int kk = 0; kk < 4; kk++){
            const int k = c * 32 + kk * 8;
            uint32_t a[2][4], b[4][2];
#pragma unroll
            for (int ma = 0; ma < 2; ma++){
                const uint32_t* ap = Hu + (rb2 + ma * 16 + g) * HW + k + t;
                a[ma][0] = ap[0];
                a[ma][1] = ap[8 * HW];
                a[ma][2] = ap[4];
                a[ma][3] = ap[8 * HW + 4];
            }
#pragma unroll
            for (int na = 0; na < 4; na++){
                const float* bp = Bb + (kk * 8 + t) * B2W + nb2 + na * 8 + g;
                b[na][0] = tf32b(bp[0]);
                b[na][1] = tf32b(bp[4 * B2W]);
            }
#pragma unroll
            for (int ma = 0; ma < 2; ma++)
#pragma unroll
                for (int na = 0; na < 4; na++)
                    mma8(acc2[ma][na], a[ma], b[na]);
        }
        __syncthreads();
        if (c < 6){ copyB2(c + 2, buf); cp_commit(); }
    }

    // ========= epilogue 2: out = D2 + b2 + edge residual (guarded) =========
#pragma unroll
    for (int ma = 0; ma < 2; ma++){
#pragma unroll
        for (int half = 0; half < 2; half++){
            const int r0 = rb2 + ma * 16 + g + half * 8;
            const int rg = row0 + r0;
            if (rg < E){
#pragma unroll
                for (int na = 0; na < 4; na++){
                    const int col = nb2 + na * 8 + 2 * t;
                    const float2 bv = *reinterpret_cast<const float2*>(b2 + col);
                    const float2 ea = *reinterpret_cast<const float2*>(
                                          edg + (size_t)rg * NF + col);
                    float2 v;
                    v.x = acc2[ma][na][half * 2 + 0] + bv.x + ea.x;
                    v.y = acc2[ma][na][half * 2 + 1] + bv.y + ea.y;
                    *reinterpret_cast<float2*>(out + (size_t)rg * NF + col) = v;
                }
            }
        }
    }
}

// ---------------------------------------------------------------------------
// inputs: 0=src 1=dest 2=edge_attr 3=u(unused) 4=batch(unused) 5=W1 6=b1 7=W2 8=b2
// ---------------------------------------------------------------------------
extern "C" void kernel_launch(void* const* d_in, const int* in_sizes, int n_in,
                              void* d_out, int out_size)
{
    const float* src  = (const float*)d_in[0];
    const float* dst  = (const float*)d_in[1];
    const float* edge = (const float*)d_in[2];
    const float* W1   = (const float*)d_in[5];
    const float* b1   = (const float*)d_in[6];
    const float* W2   = (const float*)d_in[7];
    const float* b2   = (const float*)d_in[8];
    float* out = (float*)d_out;

    const int E = in_sizes[0] / NF;

    cudaFuncSetAttribute(edge_mlp_mma,
                         cudaFuncAttributeMaxDynamicSharedMemorySize, SMEM_BYTES);

    const int grid = (E + BM - 1) / BM;
    edge_mlp_mma<<<grid, NTH, SMEM_BYTES>>>(src, dst, edge, W1, b1, W2, b2, out, E);
}

// round 7
// speedup vs baseline: 9.2673x; 1.6911x over previous
#include <cuda_runtime.h>
#include <cuda_fp16.h>
#include <cstdint>

#define NF   128
#define HID  256
#define NTH  256
#define BM   128

// smem geometry in halves; pitches give conflict-free 4B-word access
#define AW    40            // A chunk [128 r][32 k] pitch 40  (word stride 20)
#define BW    40            // B chunks [n][32 k]    pitch 40
#define HWD   264           // H [128 r][256 k]      pitch 264 (word stride 132)

#define A_SZ   (128 * AW)       // 5120 halves / buffer
#define B1_SZ  (256 * BW)       // 10240
#define B2_SZ  (128 * BW)       // 5120
#define H_SZ   (128 * HWD)      // 33792

#define OFF_A   0
#define OFF_B1  (2 * A_SZ)              // 10240
#define OFF_H   0                        // overlays phase-1 A/B1 (ends 30720)
#define OFF_B2  (OFF_H + H_SZ)           // 33792 (disjoint from H and phase-1)
#define SMEM_HALVES (OFF_B2 + 2 * B2_SZ) // 44032
#define SMEM_BYTES  (SMEM_HALVES * 2)    // 88064

// preconverted/transposed weights: W1T[n][k] 256x384, W2T[n][k] 128x256
__device__ __half g_W1T[256 * 384];
__device__ __half g_W2T[128 * 256];

// ---------------------------------------------------------------------------
static __device__ __forceinline__ uint32_t s2u(const void* p){
    uint32_t a;
    asm("{ .reg .u64 t; cvta.to.shared.u64 t, %1; cvt.u32.u64 %0, t; }" : "=r"(a) : "l"(p));
    return a;
}
static __device__ __forceinline__ uint32_t ld32s(const __half* p){
    return *reinterpret_cast<const uint32_t*>(p);
}
static __device__ __forceinline__ void cp16(uint32_t d, const void* g){
    asm volatile("cp.async.ca.shared.global [%0], [%1], 16;" :: "r"(d), "l"(g) : "memory");
}
static __device__ __forceinline__ void cp_commit(){
    asm volatile("cp.async.commit_group;" ::: "memory");
}
static __device__ __forceinline__ void cp_wait1(){
    asm volatile("cp.async.wait_group 1;" ::: "memory");
}
static __device__ __forceinline__ void cp_wait0(){
    asm volatile("cp.async.wait_group 0;" ::: "memory");
}
// D(f32x4) += A(f16 16x16) * B(f16 16x8)
static __device__ __forceinline__ void mma16(float* c, const uint32_t* a,
                                             uint32_t b0, uint32_t b1){
    asm volatile("mma.sync.aligned.m16n8k16.row.col.f32.f16.f16.f32 "
        "{%0,%1,%2,%3}, {%4,%5,%6,%7}, {%8,%9}, {%0,%1,%2,%3};"
        : "+f"(c[0]), "+f"(c[1]), "+f"(c[2]), "+f"(c[3])
        : "r"(a[0]), "r"(a[1]), "r"(a[2]), "r"(a[3]), "r"(b0), "r"(b1));
}
static __device__ __forceinline__ uint32_t pack2(float x, float y){
    __half2 h = __floats2half2_rn(x, y);
    return *reinterpret_cast<uint32_t*>(&h);
}

// ---------------------------------------------------------------------------
// prep: W1[384,256] -> W1T[256][384] half ; W2[256,128] -> W2T[128][256] half
// ---------------------------------------------------------------------------
__global__ void prep_weights(const float* __restrict__ W1, const float* __restrict__ W2){
    const int i = blockIdx.x * blockDim.x + threadIdx.x;
    if (i < 384 * 256){
        int k = i >> 8, n = i & 255;
        g_W1T[n * 384 + k] = __float2half_rn(W1[i]);
    } else {
        int j = i - 384 * 256;
        if (j < 256 * 128){
            int k = j >> 7, n = j & 127;
            g_W2T[n * 256 + k] = __float2half_rn(W2[j]);
        }
    }
}

// ---------------------------------------------------------------------------
// fused edge-MLP: out = relu([src,dst,edge] @ W1 + b1) @ W2 + b2 + edge
// ---------------------------------------------------------------------------
__global__ void __launch_bounds__(NTH, 1)
edge_mlp_h(const float* __restrict__ src, const float* __restrict__ dst,
           const float* __restrict__ edg, const float* __restrict__ b1,
           const float* __restrict__ b2,  float* __restrict__ out, int E)
{
    extern __shared__ __half sh[];
    __half* Ah  = sh + OFF_A;
    __half* B1h = sh + OFF_B1;
    __half* Hh  = sh + OFF_H;
    __half* B2h = sh + OFF_B2;

    const int tid  = threadIdx.x;
    const int lane = tid & 31, wid = tid >> 5;
    const int g = lane >> 2, t = lane & 3;
    const int row0 = blockIdx.x * BM;

    // ---- staging helpers ----
    // A chunk c: X[:, c*32 .. +32] (from src/dst/edge), fp32 LDG -> half STS
    auto ldgA = [&](int c, float4* v){
        const float* xp = (c < 4) ? src : (c < 8) ? dst : edg;
        const int cb = (c & 3) * 32;
#pragma unroll
        for (int i = 0; i < 4; i++){
            int lin = tid + i * NTH;         // 0..1023
            int kq = lin & 7, r = lin >> 3;  // kq: 4-float group, r: row
            int rg = row0 + r;
            v[i] = (rg < E) ? *reinterpret_cast<const float4*>(
                                  xp + (size_t)rg * NF + cb + kq * 4)
                            : make_float4(0.f, 0.f, 0.f, 0.f);
        }
    };
    auto stsA = [&](const float4* v, int buf){
        __half* d = Ah + buf * A_SZ;
#pragma unroll
        for (int i = 0; i < 4; i++){
            int lin = tid + i * NTH;
            int kq = lin & 7, r = lin >> 3;
            uint2 p;
            p.x = pack2(v[i].x, v[i].y);
            p.y = pack2(v[i].z, v[i].w);
            *reinterpret_cast<uint2*>(d + r * AW + kq * 4) = p;
        }
    };
    auto cpB1 = [&](int c, int buf){      // W1T rows [n][c*32 .. +32]
        __half* d = B1h + buf * B1_SZ;
#pragma unroll
        for (int i = 0; i < 4; i++){
            int lin = tid + i * NTH;      // 0..1023
            int n = lin >> 2, q = lin & 3;
            cp16(s2u(d + n * BW + q * 8), g_W1T + n * 384 + c * 32 + q * 8);
        }
    };
    auto cpB2 = [&](int c, int buf){      // W2T rows [n][c*32 .. +32]
        __half* d = B2h + buf * B2_SZ;
#pragma unroll
        for (int i = 0; i < 2; i++){
            int lin = tid + i * NTH;      // 0..511
            int n = lin >> 2, q = lin & 3;
            cp16(s2u(d + n * BW + q * 8), g_W2T + n * 256 + c * 32 + q * 8);
        }
    };

    // =================== phase 1: D1 = X @ W1  (K = 384) ===================
    const int rb = (wid & 1) * 64;        // 2 x 4 warp grid, tile 64 x 64
    const int nb = (wid >> 1) * 64;

    float acc[4][8][4];
#pragma unroll
    for (int ma = 0; ma < 4; ma++)
#pragma unroll
        for (int na = 0; na < 8; na++)
#pragma unroll
            for (int q = 0; q < 4; q++) acc[ma][na][q] = 0.f;

    float4 av[4];
    ldgA(0, av); stsA(av, 0);
    cpB1(0, 0); cp_commit();
    ldgA(1, av);
    cpB1(1, 1); cp_commit();

    for (int c = 0; c < 12; c++){
        const int buf = c & 1;
        if (c < 11) cp_wait1(); else cp_wait0();
        __syncthreads();
        const __half* Ab = Ah + buf * A_SZ;
        const __half* Bb = B1h + buf * B1_SZ;
#pragma unroll
        for (int s = 0; s < 2; s++){
            const int k0 = s * 16;
            uint32_t a[4][4];
#pragma unroll
            for (int ma = 0; ma < 4; ma++){
                const __half* ap = Ab + (rb + ma * 16 + g) * AW + k0 + 2 * t;
                a[ma][0] = ld32s(ap);
                a[ma][1] = ld32s(ap + 8 * AW);
                a[ma][2] = ld32s(ap + 8);
                a[ma][3] = ld32s(ap + 8 * AW + 8);
            }
#pragma unroll
            for (int na = 0; na < 8; na++){
                const __half* bp = Bb + (nb + na * 8 + g) * BW + k0 + 2 * t;
                uint32_t b0 = ld32s(bp), b1r = ld32s(bp + 8);
#pragma unroll
                for (int ma = 0; ma < 4; ma++)
                    mma16(acc[ma][na], a[ma], b0, b1r);
            }
        }
        __syncthreads();                  // all reads of this buffer done
        if (c < 11){
            stsA(av, buf ^ 1);            // A chunk c+1 -> other buffer
            if (c < 10){ ldgA(c + 2, av); cpB1(c + 2, buf); cp_commit(); }
        }
    }

    // ====== epilogue 1: H = half(relu(D1 + b1)) -> smem (overlays A/B1) =====
    cpB2(0, 0); cp_commit();
#pragma unroll
    for (int na = 0; na < 8; na++){
        const int col = nb + na * 8 + 2 * t;
        const float2 bv = *reinterpret_cast<const float2*>(b1 + col);
#pragma unroll
        for (int ma = 0; ma < 4; ma++){
            const int r0 = rb + ma * 16 + g;
            *reinterpret_cast<uint32_t*>(Hh + r0 * HWD + col) =
                pack2(fmaxf(acc[ma][na][0] + bv.x, 0.f),
                      fmaxf(acc[ma][na][1] + bv.y, 0.f));
            *reinterpret_cast<uint32_t*>(Hh + (r0 + 8) * HWD + col) =
                pack2(fmaxf(acc[ma][na][2] + bv.x, 0.f),
                      fmaxf(acc[ma][na][3] + bv.y, 0.f));
        }
    }
    cpB2(1, 1); cp_commit();
    __syncthreads();                      // H visible to all warps

    // =================== phase 2: D2 = H @ W2  (K = 256) ===================
    const int rb2 = (wid & 3) * 32;       // 4 x 2 warp grid, tile 32 x 64
    const int nb2 = (wid >> 2) * 64;

    float ac2[2][8][4];
#pragma unroll
    for (int ma = 0; ma < 2; ma++)
#pragma unroll
        for (int na = 0; na < 8; na++)
#pragma unroll
            for (int q = 0; q < 4; q++) ac2[ma][na][q] = 0.f;

    for (int c = 0; c < 8; c++){
        const int buf = c & 1;
        if (c < 7) cp_wait1(); else cp_wait0();
        __syncthreads();
        const __half* Bb = B2h + buf * B2_SZ;
#pragma unroll
        for (int s = 0; s < 2; s++){
            const int k = c * 32 + s * 16;
            uint32_t a[2][4];
#pragma unroll
            for (int ma = 0; ma < 2; ma++){
                const __half* ap = Hh + (rb2 + ma * 16 + g) * HWD + k + 2 * t;
                a[ma][0] = ld32s(ap);
                a[ma][1] = ld32s(ap + 8 * HWD);
                a[ma][2] = ld32s(ap + 8);
                a[ma][3] = ld32s(ap + 8 * HWD + 8);
            }
#pragma unroll
            for (int na = 0; na < 8; na++){
                const __half* bp = Bb + (nb2 + na * 8 + g) * BW + (s * 16) + 2 * t;
                uint32_t b0 = ld32s(bp), b1r = ld32s(bp + 8);
#pragma unroll
                for (int ma = 0; ma < 2; ma++)
                    mma16(ac2[ma][na], a[ma], b0, b1r);
            }
        }
        __syncthreads();
        if (c < 6){ cpB2(c + 2, buf); cp_commit(); }
    }

    // ========= epilogue 2: out = D2 + b2 + edge residual (guarded) =========
#pragma unroll
    for (int ma = 0; ma < 2; ma++){
#pragma unroll
        for (int half = 0; half < 2; half++){
            const int rg = row0 + rb2 + ma * 16 + g + half * 8;
            if (rg < E){
#pragma unroll
                for (int na = 0; na < 8; na++){
                    const int col = nb2 + na * 8 + 2 * t;
                    const float2 bv = *reinterpret_cast<const float2*>(b2 + col);
                    const float2 ea = *reinterpret_cast<const float2*>(
                                          edg + (size_t)rg * NF + col);
                    float2 v;
                    v.x = ac2[ma][na][half * 2 + 0] + bv.x + ea.x;
                    v.y = ac2[ma][na][half * 2 + 1] + bv.y + ea.y;
                    *reinterpret_cast<float2*>(out + (size_t)rg * NF + col) = v;
                }
            }
        }
    }
}

// ---------------------------------------------------------------------------
// inputs: 0=src 1=dest 2=edge_attr 3=u(unused) 4=batch(unused) 5=W1 6=b1 7=W2 8=b2
// ---------------------------------------------------------------------------
extern "C" void kernel_launch(void* const* d_in, const int* in_sizes, int n_in,
                              void* d_out, int out_size)
{
    const float* src  = (const float*)d_in[0];
    const float* dst  = (const float*)d_in[1];
    const float* edge = (const float*)d_in[2];
    const float* W1   = (const float*)d_in[5];
    const float* b1   = (const float*)d_in[6];
    const float* W2   = (const float*)d_in[7];
    const float* b2   = (const float*)d_in[8];
    float* out = (float*)d_out;

    const int E = in_sizes[0] / NF;

    prep_weights<<<(384 * 256 + 256 * 128 + 255) / 256, 256>>>(W1, W2);

    cudaFuncSetAttribute(edge_mlp_h,
                         cudaFuncAttributeMaxDynamicSharedMemorySize, SMEM_BYTES);
    const int grid = (E + BM - 1) / BM;
    edge_mlp_h<<<grid, NTH, SMEM_BYTES>>>(src, dst, edge, b1, b2, out, E);
}

// round 8
// speedup vs baseline: 11.1707x; 1.2054x over previous
#include <cuda_runtime.h>
#include <cuda_fp16.h>
#include <cstdint>

#define NF   128
#define HID  256
#define NTH  256
#define BM   128

// smem (halves). Pitches: 72 halves = 144B = 9x16B ; 264 halves = 528B = 33x16B
#define AW    72            // A chunk [128 r][64 k]
#define BW    72            // B chunks [n][64 k]
#define HWD   264           // H [128 r][256 k]

#define A_SZ   (128 * AW)       // 9216 halves / buffer
#define B1_SZ  (256 * BW)       // 18432
#define B2_SZ  (128 * BW)       // 9216
#define H_SZ   (128 * HWD)      // 33792

#define OFF_A   0
#define OFF_B1  (2 * A_SZ)              // 18432
#define OFF_H   0                        // overlays phase-1 region
#define OFF_B2  H_SZ                     // 33792 ; +2*B2_SZ = 52224 < 55296
#define SMEM_HALVES (OFF_B1 + 2 * B1_SZ) // 55296
#define SMEM_BYTES  (SMEM_HALVES * 2)    // 110592

// preconverted/transposed weights: W1T[n][k] 256x384, W2T[n][k] 128x256
__device__ __half g_W1T[256 * 384];
__device__ __half g_W2T[128 * 256];

// ---------------------------------------------------------------------------
static __device__ __forceinline__ uint32_t s2u(const void* p){
    uint32_t a;
    asm("{ .reg .u64 t; cvta.to.shared.u64 t, %1; cvt.u32.u64 %0, t; }" : "=r"(a) : "l"(p));
    return a;
}
static __device__ __forceinline__ void cp16(uint32_t d, const void* g){
    asm volatile("cp.async.ca.shared.global [%0], [%1], 16;" :: "r"(d), "l"(g) : "memory");
}
static __device__ __forceinline__ void cp_commit(){
    asm volatile("cp.async.commit_group;" ::: "memory");
}
static __device__ __forceinline__ void cp_wait1(){
    asm volatile("cp.async.wait_group 1;" ::: "memory");
}
static __device__ __forceinline__ void cp_wait0(){
    asm volatile("cp.async.wait_group 0;" ::: "memory");
}
// 4x 8x8 b16 matrices, non-transposed
static __device__ __forceinline__ void ldsm4(uint32_t* r, uint32_t addr){
    asm volatile("ldmatrix.sync.aligned.m8n8.x4.shared.b16 {%0,%1,%2,%3}, [%4];"
        : "=r"(r[0]), "=r"(r[1]), "=r"(r[2]), "=r"(r[3]) : "r"(addr));
}
// D(f32x4) += A(f16 16x16) * B(f16 16x8)
static __device__ __forceinline__ void mma16(float* c, const uint32_t* a,
                                             uint32_t b0, uint32_t b1){
    asm volatile("mma.sync.aligned.m16n8k16.row.col.f32.f16.f16.f32 "
        "{%0,%1,%2,%3}, {%4,%5,%6,%7}, {%8,%9}, {%0,%1,%2,%3};"
        : "+f"(c[0]), "+f"(c[1]), "+f"(c[2]), "+f"(c[3])
        : "r"(a[0]), "r"(a[1]), "r"(a[2]), "r"(a[3]), "r"(b0), "r"(b1));
}
static __device__ __forceinline__ uint32_t pack2(float x, float y){
    __half2 h = __floats2half2_rn(x, y);
    return *reinterpret_cast<uint32_t*>(&h);
}

// ---------------------------------------------------------------------------
__global__ void prep_weights(const float* __restrict__ W1, const float* __restrict__ W2){
    const int i = blockIdx.x * blockDim.x + threadIdx.x;
    if (i < 384 * 256){
        int k = i >> 8, n = i & 255;
        g_W1T[n * 384 + k] = __float2half_rn(W1[i]);
    } else {
        int j = i - 384 * 256;
        if (j < 256 * 128){
            int k = j >> 7, n = j & 127;
            g_W2T[n * 256 + k] = __float2half_rn(W2[j]);
        }
    }
}

// ---------------------------------------------------------------------------
// fused edge-MLP: out = relu([src,dst,edge] @ W1 + b1) @ W2 + b2 + edge
// ---------------------------------------------------------------------------
__global__ void __launch_bounds__(NTH, 1)
edge_mlp_h2(const float* __restrict__ src, const float* __restrict__ dst,
            const float* __restrict__ edg, const float* __restrict__ b1,
            const float* __restrict__ b2,  float* __restrict__ out, int E)
{
    extern __shared__ __half sh[];
    const uint32_t sb = s2u(sh);
    __half* Ah  = sh + OFF_A;
    __half* Hh  = sh + OFF_H;

    const int tid  = threadIdx.x;
    const int lane = tid & 31, wid = tid >> 5;
    const int g = lane >> 2, t = lane & 3;
    const int row0 = blockIdx.x * BM;

    // ---- staging helpers (K-chunk = 64) ----
    auto ldgA = [&](int c, float4* v){           // X[:, c*64 .. +64] fp32
        const float* xp = (c < 2) ? src : (c < 4) ? dst : edg;
        const int cb = (c & 1) * 64;
#pragma unroll
        for (int i = 0; i < 8; i++){
            int lin = tid + i * NTH;             // 0..2047
            int kq = lin & 15, r = lin >> 4;
            int rg = row0 + r;
            v[i] = (rg < E) ? *reinterpret_cast<const float4*>(
                                  xp + (size_t)rg * NF + cb + kq * 4)
                            : make_float4(0.f, 0.f, 0.f, 0.f);
        }
    };
    auto stsA = [&](const float4* v, int buf){
        __half* d = Ah + buf * A_SZ;
#pragma unroll
        for (int i = 0; i < 8; i++){
            int lin = tid + i * NTH;
            int kq = lin & 15, r = lin >> 4;
            uint2 p;
            p.x = pack2(v[i].x, v[i].y);
            p.y = pack2(v[i].z, v[i].w);
            *reinterpret_cast<uint2*>(d + r * AW + kq * 4) = p;
        }
    };
    auto cpB1 = [&](int c, int buf){             // W1T[n][c*64 .. +64]
        const uint32_t d = sb + (OFF_B1 + buf * B1_SZ) * 2;
#pragma unroll
        for (int i = 0; i < 8; i++){
            int lin = tid + i * NTH;             // 0..2047
            int q = lin & 7, n = lin >> 3;
            cp16(d + (uint32_t)(n * BW + q * 8) * 2, g_W1T + n * 384 + c * 64 + q * 8);
        }
    };
    auto cpB2 = [&](int c, int buf){             // W2T[n][c*64 .. +64]
        const uint32_t d = sb + (OFF_B2 + buf * B2_SZ) * 2;
#pragma unroll
        for (int i = 0; i < 4; i++){
            int lin = tid + i * NTH;             // 0..1023
            int q = lin & 7, n = lin >> 3;
            cp16(d + (uint32_t)(n * BW + q * 8) * 2, g_W2T + n * 256 + c * 64 + q * 8);
        }
    };

    // =================== phase 1: D1 = X @ W1  (K=384, 6 chunks) ===========
    const int rb = (wid & 1) * 64;               // 2M x 4N warp grid, tile 64x64
    const int nb = (wid >> 1) * 64;

    // per-lane ldmatrix offsets (bytes)
    const uint32_t aOff = (uint32_t)(((rb + (lane & 15)) * AW + (lane >> 4) * 8)) * 2;
    const uint32_t bOff1 = (uint32_t)(((nb + (lane >> 4) * 8 + (lane & 7)) * BW
                                       + ((lane >> 3) & 1) * 8)) * 2;

    float acc[4][8][4];
#pragma unroll
    for (int ma = 0; ma < 4; ma++)
#pragma unroll
        for (int na = 0; na < 8; na++)
#pragma unroll
            for (int q = 0; q < 4; q++) acc[ma][na][q] = 0.f;

    float4 av[8];
    ldgA(0, av); stsA(av, 0);
    cpB1(0, 0); cp_commit();
    ldgA(1, av);
    cpB1(1, 1); cp_commit();

    for (int c = 0; c < 6; c++){
        const int buf = c & 1;
        if (c < 5) cp_wait1(); else cp_wait0();
        __syncthreads();                          // buffer ready for all
        const uint32_t aB = sb + (OFF_A + buf * A_SZ) * 2 + aOff;
        const uint32_t bB = sb + (OFF_B1 + buf * B1_SZ) * 2 + bOff1;
#pragma unroll
        for (int s = 0; s < 4; s++){
            uint32_t a[4][4], bf[4][4];
#pragma unroll
            for (int ma = 0; ma < 4; ma++)
                ldsm4(a[ma], aB + (uint32_t)(ma * 16 * AW) * 2 + s * 32);
#pragma unroll
            for (int p = 0; p < 4; p++)
                ldsm4(bf[p], bB + (uint32_t)(p * 16 * BW) * 2 + s * 32);
#pragma unroll
            for (int p = 0; p < 4; p++)
#pragma unroll
                for (int ma = 0; ma < 4; ma++){
                    mma16(acc[ma][2 * p + 0], a[ma], bf[p][0], bf[p][1]);
                    mma16(acc[ma][2 * p + 1], a[ma], bf[p][2], bf[p][3]);
                }
        }
        __syncthreads();                          // reads of this buffer done
        if (c < 5){
            stsA(av, buf ^ 1);                    // chunk c+1 -> other buffer
            if (c < 4){ ldgA(c + 2, av); cpB1(c + 2, buf); cp_commit(); }
        }
    }

    // ====== epilogue 1: H = half(relu(D1 + b1)) -> smem (overlays) =========
    cpB2(0, 0); cp_commit();
#pragma unroll
    for (int na = 0; na < 8; na++){
        const int col = nb + na * 8 + 2 * t;
        const float2 bv = *reinterpret_cast<const float2*>(b1 + col);
#pragma unroll
        for (int ma = 0; ma < 4; ma++){
            const int r0 = rb + ma * 16 + g;
            *reinterpret_cast<uint32_t*>(Hh + r0 * HWD + col) =
                pack2(fmaxf(acc[ma][na][0] + bv.x, 0.f),
                      fmaxf(acc[ma][na][1] + bv.y, 0.f));
            *reinterpret_cast<uint32_t*>(Hh + (r0 + 8) * HWD + col) =
                pack2(fmaxf(acc[ma][na][2] + bv.x, 0.f),
                      fmaxf(acc[ma][na][3] + bv.y, 0.f));
        }
    }
    cpB2(1, 1); cp_commit();

    // =================== phase 2: D2 = H @ W2  (K=256, 4 chunks) ===========
    const int rb2 = (wid & 3) * 32;              // 4M x 2N warp grid, tile 32x64
    const int nb2 = (wid >> 2) * 64;

    const uint32_t aOff2 = (uint32_t)(((rb2 + (lane & 15)) * HWD + (lane >> 4) * 8)) * 2;
    const uint32_t bOff2 = (uint32_t)(((nb2 + (lane >> 4) * 8 + (lane & 7)) * BW
                                       + ((lane >> 3) & 1) * 8)) * 2;

    float ac2[2][8][4];
#pragma unroll
    for (int ma = 0; ma < 2; ma++)
#pragma unroll
        for (int na = 0; na < 8; na++)
#pragma unroll
            for (int q = 0; q < 4; q++) ac2[ma][na][q] = 0.f;

    for (int c2 = 0; c2 < 4; c2++){
        const int buf = c2 & 1;
        if (c2 < 3) cp_wait1(); else cp_wait0();
        __syncthreads();                          // also fences H on c2==0
        const uint32_t aB = sb + OFF_H * 2 + aOff2 + (uint32_t)(c2 * 64) * 2;
        const uint32_t bB = sb + (OFF_B2 + buf * B2_SZ) * 2 + bOff2;
#pragma unroll
        for (int s = 0; s < 4; s++){
            uint32_t a[2][4], bf[4][4];
#pragma unroll
            for (int ma = 0; ma < 2; ma++)
                ldsm4(a[ma], aB + (uint32_t)(ma * 16 * HWD) * 2 + s * 32);
#pragma unroll
            for (int p = 0; p < 4; p++)
                ldsm4(bf[p], bB + (uint32_t)(p * 16 * BW) * 2 + s * 32);
#pragma unroll
            for (int p = 0; p < 4; p++)
#pragma unroll
                for (int ma = 0; ma < 2; ma++){
                    mma16(ac2[ma][2 * p + 0], a[ma], bf[p][0], bf[p][1]);
                    mma16(ac2[ma][2 * p + 1], a[ma], bf[p][2], bf[p][3]);
                }
        }
        __syncthreads();
        if (c2 < 2){ cpB2(c2 + 2, buf); cp_commit(); }
    }

    // ========= epilogue 2: out = D2 + b2 + edge residual (guarded) =========
#pragma unroll
    for (int ma = 0; ma < 2; ma++){
#pragma unroll
        for (int half = 0; half < 2; half++){
            const int rg = row0 + rb2 + ma * 16 + g + half * 8;
            if (rg < E){
#pragma unroll
                for (int na = 0; na < 8; na++){
                    const int col = nb2 + na * 8 + 2 * t;
                    const float2 bv = *reinterpret_cast<const float2*>(b2 + col);
                    const float2 ea = *reinterpret_cast<const float2*>(
                                          edg + (size_t)rg * NF + col);
                    float2 v;
                    v.x = ac2[ma][na][half * 2 + 0] + bv.x + ea.x;
                    v.y = ac2[ma][na][half * 2 + 1] + bv.y + ea.y;
                    *reinterpret_cast<float2*>(out + (size_t)rg * NF + col) = v;
                }
            }
        }
    }
}

// ---------------------------------------------------------------------------
// inputs: 0=src 1=dest 2=edge_attr 3=u(unused) 4=batch(unused) 5=W1 6=b1 7=W2 8=b2
// ---------------------------------------------------------------------------
extern "C" void kernel_launch(void* const* d_in, const int* in_sizes, int n_in,
                              void* d_out, int out_size)
{
    const float* src  = (const float*)d_in[0];
    const float* dst  = (const float*)d_in[1];
    const float* edge = (const float*)d_in[2];
    const float* W1   = (const float*)d_in[5];
    const float* b1   = (const float*)d_in[6];
    const float* W2   = (const float*)d_in[7];
    const float* b2   = (const float*)d_in[8];
    float* out = (float*)d_out;

    const int E = in_sizes[0] / NF;

    prep_weights<<<(384 * 256 + 256 * 128 + 255) / 256, 256>>>(W1, W2);

    cudaFuncSetAttribute(edge_mlp_h2,
                         cudaFuncAttributeMaxDynamicSharedMemorySize, SMEM_BYTES);
    const int grid = (E + BM - 1) / BM;
    edge_mlp_h2<<<grid, NTH, SMEM_BYTES>>>(src, dst, edge, b1, b2, out, E);
}

// round 9
// speedup vs baseline: 11.3575x; 1.0167x over previous
#include <cuda_runtime.h>
#include <cuda_fp16.h>
#include <cstdint>

#define NF   128
#define HID  256
#define NTH  512
#define BM   128

// smem (halves). Pitches: 72 halves = 144B = 9x16B ; 264 halves = 528B = 33x16B
#define AW    72            // A chunk [128 r][64 k]
#define BW    72            // B chunks [n][64 k]
#define HWD   264           // H [128 r][256 k]

#define A_SZ   (128 * AW)       // 9216 halves / buffer
#define B1_SZ  (256 * BW)       // 18432
#define B2_SZ  (128 * BW)       // 9216
#define H_SZ   (128 * HWD)      // 33792

#define OFF_A   0
#define OFF_B1  (2 * A_SZ)              // 18432
#define OFF_H   0                        // overlays phase-1 region
#define OFF_B2  H_SZ                     // 33792 ; +2*B2_SZ = 52224 < 55296
#define SMEM_HALVES (OFF_B1 + 2 * B1_SZ) // 55296
#define SMEM_BYTES  (SMEM_HALVES * 2)    // 110592

// preconverted/transposed weights: W1T[n][k] 256x384, W2T[n][k] 128x256
__device__ __half g_W1T[256 * 384];
__device__ __half g_W2T[128 * 256];

// ---------------------------------------------------------------------------
static __device__ __forceinline__ uint32_t s2u(const void* p){
    uint32_t a;
    asm("{ .reg .u64 t; cvta.to.shared.u64 t, %1; cvt.u32.u64 %0, t; }" : "=r"(a) : "l"(p));
    return a;
}
static __device__ __forceinline__ void cp16(uint32_t d, const void* g){
    asm volatile("cp.async.ca.shared.global [%0], [%1], 16;" :: "r"(d), "l"(g) : "memory");
}
static __device__ __forceinline__ void cp_commit(){
    asm volatile("cp.async.commit_group;" ::: "memory");
}
static __device__ __forceinline__ void cp_wait1(){
    asm volatile("cp.async.wait_group 1;" ::: "memory");
}
static __device__ __forceinline__ void cp_wait0(){
    asm volatile("cp.async.wait_group 0;" ::: "memory");
}
// 4x 8x8 b16 matrices, non-transposed
static __device__ __forceinline__ void ldsm4(uint32_t* r, uint32_t addr){
    asm volatile("ldmatrix.sync.aligned.m8n8.x4.shared.b16 {%0,%1,%2,%3}, [%4];"
        : "=r"(r[0]), "=r"(r[1]), "=r"(r[2]), "=r"(r[3]) : "r"(addr));
}
// D(f32x4) += A(f16 16x16) * B(f16 16x8)
static __device__ __forceinline__ void mma16(float* c, const uint32_t* a,
                                             uint32_t b0, uint32_t b1){
    asm volatile("mma.sync.aligned.m16n8k16.row.col.f32.f16.f16.f32 "
        "{%0,%1,%2,%3}, {%4,%5,%6,%7}, {%8,%9}, {%0,%1,%2,%3};"
        : "+f"(c[0]), "+f"(c[1]), "+f"(c[2]), "+f"(c[3])
        : "r"(a[0]), "r"(a[1]), "r"(a[2]), "r"(a[3]), "r"(b0), "r"(b1));
}
static __device__ __forceinline__ uint32_t pack2(float x, float y){
    __half2 h = __floats2half2_rn(x, y);
    return *reinterpret_cast<uint32_t*>(&h);
}

// ---------------------------------------------------------------------------
__global__ void prep_weights(const float* __restrict__ W1, const float* __restrict__ W2){
    const int i = blockIdx.x * blockDim.x + threadIdx.x;
    if (i < 384 * 256){
        int k = i >> 8, n = i & 255;
        g_W1T[n * 384 + k] = __float2half_rn(W1[i]);
    } else {
        int j = i - 384 * 256;
        if (j < 256 * 128){
            int k = j >> 7, n = j & 127;
            g_W2T[n * 256 + k] = __float2half_rn(W2[j]);
        }
    }
}

// ---------------------------------------------------------------------------
// fused edge-MLP: out = relu([src,dst,edge] @ W1 + b1) @ W2 + b2 + edge
// ---------------------------------------------------------------------------
__global__ void __launch_bounds__(NTH, 1)
edge_mlp_h3(const float* __restrict__ src, const float* __restrict__ dst,
            const float* __restrict__ edg, const float* __restrict__ b1,
            const float* __restrict__ b2,  float* __restrict__ out, int E)
{
    extern __shared__ __half sh[];
    const uint32_t sb = s2u(sh);
    __half* Ah  = sh + OFF_A;
    __half* Hh  = sh + OFF_H;

    const int tid  = threadIdx.x;
    const int lane = tid & 31, wid = tid >> 5;
    const int g = lane >> 2, t = lane & 3;
    const int row0 = blockIdx.x * BM;

    // ---- staging helpers (K-chunk = 64) ----
    auto ldgA = [&](int c, float4* v){           // X[:, c*64 .. +64] fp32
        const float* xp = (c < 2) ? src : (c < 4) ? dst : edg;
        const int cb = (c & 1) * 64;
#pragma unroll
        for (int i = 0; i < 4; i++){
            int lin = tid + i * NTH;             // 0..2047
            int kq = lin & 15, r = lin >> 4;
            int rg = row0 + r;
            v[i] = (rg < E) ? *reinterpret_cast<const float4*>(
                                  xp + (size_t)rg * NF + cb + kq * 4)
                            : make_float4(0.f, 0.f, 0.f, 0.f);
        }
    };
    auto stsA = [&](const float4* v, int buf){
        __half* d = Ah + buf * A_SZ;
#pragma unroll
        for (int i = 0; i < 4; i++){
            int lin = tid + i * NTH;
            int kq = lin & 15, r = lin >> 4;
            uint2 p;
            p.x = pack2(v[i].x, v[i].y);
            p.y = pack2(v[i].z, v[i].w);
            *reinterpret_cast<uint2*>(d + r * AW + kq * 4) = p;
        }
    };
    auto cpB1 = [&](int c, int buf){             // W1T[n][c*64 .. +64]
        const uint32_t d = sb + (OFF_B1 + buf * B1_SZ) * 2;
#pragma unroll
        for (int i = 0; i < 4; i++){
            int lin = tid + i * NTH;             // 0..2047
            int q = lin & 7, n = lin >> 3;
            cp16(d + (uint32_t)(n * BW + q * 8) * 2, g_W1T + n * 384 + c * 64 + q * 8);
        }
    };
    auto cpB2 = [&](int c, int buf){             // W2T[n][c*64 .. +64]
        const uint32_t d = sb + (OFF_B2 + buf * B2_SZ) * 2;
#pragma unroll
        for (int i = 0; i < 2; i++){
            int lin = tid + i * NTH;             // 0..1023
            int q = lin & 7, n = lin >> 3;
            cp16(d + (uint32_t)(n * BW + q * 8) * 2, g_W2T + n * 256 + c * 64 + q * 8);
        }
    };

    // =================== phase 1: D1 = X @ W1  (K=384, 6 chunks) ===========
    const int rb = (wid & 3) * 32;               // 4M x 4N warp grid, tile 32x64
    const int nb = (wid >> 2) * 64;

    // per-lane ldmatrix offsets (bytes)
    const uint32_t aOff = (uint32_t)(((rb + (lane & 15)) * AW + (lane >> 4) * 8)) * 2;
    const uint32_t bOff1 = (uint32_t)(((nb + (lane >> 4) * 8 + (lane & 7)) * BW
                                       + ((lane >> 3) & 1) * 8)) * 2;

    float acc[2][8][4];
#pragma unroll
    for (int ma = 0; ma < 2; ma++)
#pragma unroll
        for (int na = 0; na < 8; na++)
#pragma unroll
            for (int q = 0; q < 4; q++) acc[ma][na][q] = 0.f;

    float4 av[4];
    ldgA(0, av); stsA(av, 0);
    cpB1(0, 0); cp_commit();
    ldgA(1, av);
    cpB1(1, 1); cp_commit();

    for (int c = 0; c < 6; c++){
        const int buf = c & 1;
        if (c < 5) cp_wait1(); else cp_wait0();
        __syncthreads();                          // buffer ready for all
        const uint32_t aB = sb + (OFF_A + buf * A_SZ) * 2 + aOff;
        const uint32_t bB = sb + (OFF_B1 + buf * B1_SZ) * 2 + bOff1;
#pragma unroll
        for (int s = 0; s < 4; s++){
            uint32_t a[2][4], bf[4][4];
#pragma unroll
            for (int ma = 0; ma < 2; ma++)
                ldsm4(a[ma], aB + (uint32_t)(ma * 16 * AW) * 2 + s * 32);
#pragma unroll
            for (int p = 0; p < 4; p++)
                ldsm4(bf[p], bB + (uint32_t)(p * 16 * BW) * 2 + s * 32);
#pragma unroll
            for (int p = 0; p < 4; p++)
#pragma unroll
                for (int ma = 0; ma < 2; ma++){
                    mma16(acc[ma][2 * p + 0], a[ma], bf[p][0], bf[p][1]);
                    mma16(acc[ma][2 * p + 1], a[ma], bf[p][2], bf[p][3]);
                }
        }
        __syncthreads();                          // reads of this buffer done
        if (c < 5){
            stsA(av, buf ^ 1);                    // chunk c+1 -> other buffer
            if (c < 4){ ldgA(c + 2, av); cpB1(c + 2, buf); cp_commit(); }
        }
    }

    // ====== epilogue 1: H = half(relu(D1 + b1)) -> smem (overlays) =========
    cpB2(0, 0); cp_commit();
#pragma unroll
    for (int na = 0; na < 8; na++){
        const int col = nb + na * 8 + 2 * t;
        const float2 bv = *reinterpret_cast<const float2*>(b1 + col);
#pragma unroll
        for (int ma = 0; ma < 2; ma++){
            const int r0 = rb + ma * 16 + g;
            *reinterpret_cast<uint32_t*>(Hh + r0 * HWD + col) =
                pack2(fmaxf(acc[ma][na][0] + bv.x, 0.f),
                      fmaxf(acc[ma][na][1] + bv.y, 0.f));
            *reinterpret_cast<uint32_t*>(Hh + (r0 + 8) * HWD + col) =
                pack2(fmaxf(acc[ma][na][2] + bv.x, 0.f),
                      fmaxf(acc[ma][na][3] + bv.y, 0.f));
        }
    }
    cpB2(1, 1); cp_commit();

    // =================== phase 2: D2 = H @ W2  (K=256, 4 chunks) ===========
    const int rb2 = (wid & 3) * 32;              // 4M x 4N warp grid, tile 32x32
    const int nb2 = (wid >> 2) * 32;

    const uint32_t aOff2 = (uint32_t)(((rb2 + (lane & 15)) * HWD + (lane >> 4) * 8)) * 2;
    const uint32_t bOff2 = (uint32_t)(((nb2 + (lane >> 4) * 8 + (lane & 7)) * BW
                                       + ((lane >> 3) & 1) * 8)) * 2;

    float ac2[2][4][4];
#pragma unroll
    for (int ma = 0; ma < 2; ma++)
#pragma unroll
        for (int na = 0; na < 4; na++)
#pragma unroll
            for (int q = 0; q < 4; q++) ac2[ma][na][q] = 0.f;

    for (int c2 = 0; c2 < 4; c2++){
        const int buf = c2 & 1;
        if (c2 < 3) cp_wait1(); else cp_wait0();
        __syncthreads();                          // also fences H on c2==0
        const uint32_t aB = sb + OFF_H * 2 + aOff2 + (uint32_t)(c2 * 64) * 2;
        const uint32_t bB = sb + (OFF_B2 + buf * B2_SZ) * 2 + bOff2;
#pragma unroll
        for (int s = 0; s < 4; s++){
            uint32_t a[2][4], bf[2][4];
#pragma unroll
            for (int ma = 0; ma < 2; ma++)
                ldsm4(a[ma], aB + (uint32_t)(ma * 16 * HWD) * 2 + s * 32);
#pragma unroll
            for (int p = 0; p < 2; p++)
                ldsm4(bf[p], bB + (uint32_t)(p * 16 * BW) * 2 + s * 32);
#pragma unroll
            for (int p = 0; p < 2; p++)
#pragma unroll
                for (int ma = 0; ma < 2; ma++){
                    mma16(ac2[ma][2 * p + 0], a[ma], bf[p][0], bf[p][1]);
                    mma16(ac2[ma][2 * p + 1], a[ma], bf[p][2], bf[p][3]);
                }
        }
        __syncthreads();
        if (c2 < 2){ cpB2(c2 + 2, buf); cp_commit(); }
    }

    // ========= epilogue 2: out = D2 + b2 + edge residual (guarded) =========
#pragma unroll
    for (int ma = 0; ma < 2; ma++){
#pragma unroll
        for (int half = 0; half < 2; half++){
            const int rg = row0 + rb2 + ma * 16 + g + half * 8;
            if (rg < E){
#pragma unroll
                for (int na = 0; na < 4; na++){
                    const int col = nb2 + na * 8 + 2 * t;
                    const float2 bv = *reinterpret_cast<const float2*>(b2 + col);
                    const float2 ea = *reinterpret_cast<const float2*>(
                                          edg + (size_t)rg * NF + col);
                    float2 v;
                    v.x = ac2[ma][na][half * 2 + 0] + bv.x + ea.x;
                    v.y = ac2[ma][na][half * 2 + 1] + bv.y + ea.y;
                    *reinterpret_cast<float2*>(out + (size_t)rg * NF + col) = v;
                }
            }
        }
    }
}

// ---------------------------------------------------------------------------
// inputs: 0=src 1=dest 2=edge_attr 3=u(unused) 4=batch(unused) 5=W1 6=b1 7=W2 8=b2
// ---------------------------------------------------------------------------
extern "C" void kernel_launch(void* const* d_in, const int* in_sizes, int n_in,
                              void* d_out, int out_size)
{
    const float* src  = (const float*)d_in[0];
    const float* dst  = (const float*)d_in[1];
    const float* edge = (const float*)d_in[2];
    const float* W1   = (const float*)d_in[5];
    const float* b1   = (const float*)d_in[6];
    const float* W2   = (const float*)d_in[7];
    const float* b2   = (const float*)d_in[8];
    float* out = (float*)d_out;

    const int E = in_sizes[0] / NF;

    prep_weights<<<(384 * 256 + 256 * 128 + 255) / 256, 256>>>(W1, W2);

    cudaFuncSetAttribute(edge_mlp_h3,
                         cudaFuncAttributeMaxDynamicSharedMemorySize, SMEM_BYTES);
    const int grid = (E + BM - 1) / BM;
    edge_mlp_h3<<<grid, NTH, SMEM_BYTES>>>(src, dst, edge, b1, b2, out, E);
}

// round 10
// speedup vs baseline: 11.4976x; 1.0123x over previous
#include <cuda_runtime.h>
#include <cuda_fp16.h>
#include <cstdint>

#define NF   128
#define HID  256
#define NTH  512
#define BM   128

// smem (halves). Pitches: 72 halves = 144B = 9x16B ; 264 halves = 528B = 33x16B
#define AW    72            // A chunk [128 r][64 k]
#define BW    72            // B chunks [n][64 k]
#define HWD   264           // H [128 r][256 k]

#define A_SZ   (128 * AW)       // 9216 halves / buffer (x2)
#define B1_SZ  (256 * BW)       // 18432 (x3)
#define B2_SZ  (128 * BW)       // 9216 (x3)
#define H_SZ   (128 * HWD)      // 33792

#define OFF_A   0
#define OFF_B1  (2 * A_SZ)              // 18432
#define OFF_H   0                        // phase2 overlays phase-1 region
#define OFF_B2  H_SZ                     // 33792 ; +3*B2_SZ = 61440 < 73728
#define SMEM_HALVES (OFF_B1 + 3 * B1_SZ) // 73728
#define SMEM_BYTES  (SMEM_HALVES * 2)    // 147456

// preconverted/transposed weights: W1T[n][k] 256x384, W2T[n][k] 128x256
__device__ __half g_W1T[256 * 384];
__device__ __half g_W2T[128 * 256];

// ---------------------------------------------------------------------------
static __device__ __forceinline__ uint32_t s2u(const void* p){
    uint32_t a;
    asm("{ .reg .u64 t; cvta.to.shared.u64 t, %1; cvt.u32.u64 %0, t; }" : "=r"(a) : "l"(p));
    return a;
}
static __device__ __forceinline__ void cp16(uint32_t d, const void* g){
    asm volatile("cp.async.ca.shared.global [%0], [%1], 16;" :: "r"(d), "l"(g) : "memory");
}
static __device__ __forceinline__ void cp_commit(){
    asm volatile("cp.async.commit_group;" ::: "memory");
}
static __device__ __forceinline__ void cp_wait1(){
    asm volatile("cp.async.wait_group 1;" ::: "memory");
}
static __device__ __forceinline__ void cp_wait0(){
    asm volatile("cp.async.wait_group 0;" ::: "memory");
}
// 4x 8x8 b16 matrices, non-transposed
static __device__ __forceinline__ void ldsm4(uint32_t* r, uint32_t addr){
    asm volatile("ldmatrix.sync.aligned.m8n8.x4.shared.b16 {%0,%1,%2,%3}, [%4];"
        : "=r"(r[0]), "=r"(r[1]), "=r"(r[2]), "=r"(r[3]) : "r"(addr));
}
// D(f32x4) += A(f16 16x16) * B(f16 16x8)
static __device__ __forceinline__ void mma16(float* c, const uint32_t* a,
                                             uint32_t b0, uint32_t b1){
    asm volatile("mma.sync.aligned.m16n8k16.row.col.f32.f16.f16.f32 "
        "{%0,%1,%2,%3}, {%4,%5,%6,%7}, {%8,%9}, {%0,%1,%2,%3};"
        : "+f"(c[0]), "+f"(c[1]), "+f"(c[2]), "+f"(c[3])
        : "r"(a[0]), "r"(a[1]), "r"(a[2]), "r"(a[3]), "r"(b0), "r"(b1));
}
static __device__ __forceinline__ uint32_t pack2(float x, float y){
    __half2 h = __floats2half2_rn(x, y);
    return *reinterpret_cast<uint32_t*>(&h);
}

// ---------------------------------------------------------------------------
__global__ void prep_weights(const float* __restrict__ W1, const float* __restrict__ W2){
    const int i = blockIdx.x * blockDim.x + threadIdx.x;
    if (i < 384 * 256){
        int k = i >> 8, n = i & 255;
        g_W1T[n * 384 + k] = __float2half_rn(W1[i]);
    } else {
        int j = i - 384 * 256;
        if (j < 256 * 128){
            int k = j >> 7, n = j & 127;
            g_W2T[n * 256 + k] = __float2half_rn(W2[j]);
        }
    }
}

// ---------------------------------------------------------------------------
// fused edge-MLP: out = relu([src,dst,edge] @ W1 + b1) @ W2 + b2 + edge
// ---------------------------------------------------------------------------
__global__ void __launch_bounds__(NTH, 1)
edge_mlp_h4(const float* __restrict__ src, const float* __restrict__ dst,
            const float* __restrict__ edg, const float* __restrict__ b1,
            const float* __restrict__ b2,  float* __restrict__ out, int E)
{
    extern __shared__ __half sh[];
    const uint32_t sb = s2u(sh);
    __half* Ah  = sh + OFF_A;
    __half* Hh  = sh + OFF_H;

    const int tid  = threadIdx.x;
    const int lane = tid & 31, wid = tid >> 5;
    const int g = lane >> 2, t = lane & 3;
    const int row0 = blockIdx.x * BM;

    // ---- staging helpers (K-chunk = 64) ----
    auto ldgA = [&](int c, float4* v){           // X[:, c*64 .. +64] fp32
        const float* xp = (c < 2) ? src : (c < 4) ? dst : edg;
        const int cb = (c & 1) * 64;
#pragma unroll
        for (int i = 0; i < 4; i++){
            int lin = tid + i * NTH;             // 0..2047
            int kq = lin & 15, r = lin >> 4;
            int rg = row0 + r;
            v[i] = (rg < E) ? *reinterpret_cast<const float4*>(
                                  xp + (size_t)rg * NF + cb + kq * 4)
                            : make_float4(0.f, 0.f, 0.f, 0.f);
        }
    };
    auto stsA = [&](const float4* v, int buf){
        __half* d = Ah + buf * A_SZ;
#pragma unroll
        for (int i = 0; i < 4; i++){
            int lin = tid + i * NTH;
            int kq = lin & 15, r = lin >> 4;
            uint2 p;
            p.x = pack2(v[i].x, v[i].y);
            p.y = pack2(v[i].z, v[i].w);
            *reinterpret_cast<uint2*>(d + r * AW + kq * 4) = p;
        }
    };
    auto cpB1 = [&](int c, int buf){             // W1T[n][c*64 .. +64]
        const uint32_t d = sb + (uint32_t)(OFF_B1 + buf * B1_SZ) * 2;
#pragma unroll
        for (int i = 0; i < 4; i++){
            int lin = tid + i * NTH;             // 0..2047
            int q = lin & 7, n = lin >> 3;
            cp16(d + (uint32_t)(n * BW + q * 8) * 2, g_W1T + n * 384 + c * 64 + q * 8);
        }
    };
    auto cpB2 = [&](int c, int buf){             // W2T[n][c*64 .. +64]
        const uint32_t d = sb + (uint32_t)(OFF_B2 + buf * B2_SZ) * 2;
#pragma unroll
        for (int i = 0; i < 2; i++){
            int lin = tid + i * NTH;             // 0..1023
            int q = lin & 7, n = lin >> 3;
            cp16(d + (uint32_t)(n * BW + q * 8) * 2, g_W2T + n * 256 + c * 64 + q * 8);
        }
    };

    // =================== phase 1: D1 = X @ W1  (K=384, 6 chunks) ===========
    const int rb = (wid & 3) * 32;               // 4M x 4N warp grid, tile 32x64
    const int nb = (wid >> 2) * 64;

    const uint32_t aOff = (uint32_t)(((rb + (lane & 15)) * AW + (lane >> 4) * 8)) * 2;
    const uint32_t bOff1 = (uint32_t)(((nb + (lane >> 4) * 8 + (lane & 7)) * BW
                                       + ((lane >> 3) & 1) * 8)) * 2;

    float acc[2][8][4];
#pragma unroll
    for (int ma = 0; ma < 2; ma++)
#pragma unroll
        for (int na = 0; na < 8; na++)
#pragma unroll
            for (int q = 0; q < 4; q++) acc[ma][na][q] = 0.f;

    float4 av[4];
    ldgA(0, av); stsA(av, 0);                     // A chunk 0 -> buf0
    ldgA(1, av);                                  // A chunk 1 staged in regs
    cpB1(0, 0); cp_commit();
    cpB1(1, 1); cp_commit();

    for (int c = 0; c < 6; c++){
        const int p = c & 1;
        if (c < 5) cp_wait1(); else cp_wait0();   // B1 chunk c resident
        __syncthreads();                          // ONE barrier per chunk
        // overlap: stage next A chunk + issue next B cp.async during MMAs
        if (c < 5){
            stsA(av, p ^ 1);                      // A chunk c+1 -> other buffer
            if (c < 4){
                ldgA(c + 2, av);
                cpB1(c + 2, (c + 2) % 3); cp_commit();
            }
        }
        const uint32_t aB = sb + (uint32_t)(OFF_A + p * A_SZ) * 2 + aOff;
        const uint32_t bB = sb + (uint32_t)(OFF_B1 + (c % 3) * B1_SZ) * 2 + bOff1;
#pragma unroll
        for (int s = 0; s < 4; s++){
            uint32_t a[2][4], bf[4][4];
#pragma unroll
            for (int ma = 0; ma < 2; ma++)
                ldsm4(a[ma], aB + (uint32_t)(ma * 16 * AW) * 2 + s * 32);
#pragma unroll
            for (int q = 0; q < 4; q++)
                ldsm4(bf[q], bB + (uint32_t)(q * 16 * BW) * 2 + s * 32);
#pragma unroll
            for (int q = 0; q < 4; q++)
#pragma unroll
                for (int ma = 0; ma < 2; ma++){
                    mma16(acc[ma][2 * q + 0], a[ma], bf[q][0], bf[q][1]);
                    mma16(acc[ma][2 * q + 1], a[ma], bf[q][2], bf[q][3]);
                }
        }
    }
    __syncthreads();                              // phase-1 reads done (H overlays)

    // ====== epilogue 1: H = half(relu(D1 + b1)) -> smem (overlays) =========
    cpB2(0, 0); cp_commit();
#pragma unroll
    for (int na = 0; na < 8; na++){
        const int col = nb + na * 8 + 2 * t;
        const float2 bv = *reinterpret_cast<const float2*>(b1 + col);
#pragma unroll
        for (int ma = 0; ma < 2; ma++){
            const int r0 = rb + ma * 16 + g;
            *reinterpret_cast<uint32_t*>(Hh + r0 * HWD + col) =
                pack2(fmaxf(acc[ma][na][0] + bv.x, 0.f),
                      fmaxf(acc[ma][na][1] + bv.y, 0.f));
            *reinterpret_cast<uint32_t*>(Hh + (r0 + 8) * HWD + col) =
                pack2(fmaxf(acc[ma][na][2] + bv.x, 0.f),
                      fmaxf(acc[ma][na][3] + bv.y, 0.f));
        }
    }
    cpB2(1, 1); cp_commit();

    // =================== phase 2: D2 = H @ W2  (K=256, 4 chunks) ===========
    const int rb2 = (wid & 3) * 32;              // 4M x 4N warp grid, tile 32x32
    const int nb2 = (wid >> 2) * 32;

    const uint32_t aOff2 = (uint32_t)(((rb2 + (lane & 15)) * HWD + (lane >> 4) * 8)) * 2;
    const uint32_t bOff2 = (uint32_t)(((nb2 + (lane >> 4) * 8 + (lane & 7)) * BW
                                       + ((lane >> 3) & 1) * 8)) * 2;

    float ac2[2][4][4];
#pragma unroll
    for (int ma = 0; ma < 2; ma++)
#pragma unroll
        for (int na = 0; na < 4; na++)
#pragma unroll
            for (int q = 0; q < 4; q++) ac2[ma][na][q] = 0.f;

    for (int c2 = 0; c2 < 4; c2++){
        if (c2 < 3) cp_wait1(); else cp_wait0();  // B2 chunk c2 resident
        __syncthreads();                          // also fences H on c2==0
        if (c2 < 2){ cpB2(c2 + 2, (c2 + 2) % 3); cp_commit(); }
        const uint32_t aB = sb + (uint32_t)OFF_H * 2 + aOff2 + (uint32_t)(c2 * 64) * 2;
        const uint32_t bB = sb + (uint32_t)(OFF_B2 + (c2 % 3) * B2_SZ) * 2 + bOff2;
#pragma unroll
        for (int s = 0; s < 4; s++){
            uint32_t a[2][4], bf[2][4];
#pragma unroll
            for (int ma = 0; ma < 2; ma++)
                ldsm4(a[ma], aB + (uint32_t)(ma * 16 * HWD) * 2 + s * 32);
#pragma unroll
            for (int q = 0; q < 2; q++)
                ldsm4(bf[q], bB + (uint32_t)(q * 16 * BW) * 2 + s * 32);
#pragma unroll
            for (int q = 0; q < 2; q++)
#pragma unroll
                for (int ma = 0; ma < 2; ma++){
                    mma16(ac2[ma][2 * q + 0], a[ma], bf[q][0], bf[q][1]);
                    mma16(ac2[ma][2 * q + 1], a[ma], bf[q][2], bf[q][3]);
                }
        }
    }

    // ========= epilogue 2: out = D2 + b2 + edge residual (guarded) =========
#pragma unroll
    for (int ma = 0; ma < 2; ma++){
#pragma unroll
        for (int half = 0; half < 2; half++){
            const int rg = row0 + rb2 + ma * 16 + g + half * 8;
            if (rg < E){
#pragma unroll
                for (int na = 0; na < 4; na++){
                    const int col = nb2 + na * 8 + 2 * t;
                    const float2 bv = *reinterpret_cast<const float2*>(b2 + col);
                    const float2 ea = *reinterpret_cast<const float2*>(
                                          edg + (size_t)rg * NF + col);
                    float2 v;
                    v.x = ac2[ma][na][half * 2 + 0] + bv.x + ea.x;
                    v.y = ac2[ma][na][half * 2 + 1] + bv.y + ea.y;
                    *reinterpret_cast<float2*>(out + (size_t)rg * NF + col) = v;
                }
            }
        }
    }
}

// ---------------------------------------------------------------------------
// inputs: 0=src 1=dest 2=edge_attr 3=u(unused) 4=batch(unused) 5=W1 6=b1 7=W2 8=b2
// ---------------------------------------------------------------------------
extern "C" void kernel_launch(void* const* d_in, const int* in_sizes, int n_in,
                              void* d_out, int out_size)
{
    const float* src  = (const float*)d_in[0];
    const float* dst  = (const float*)d_in[1];
    const float* edge = (const float*)d_in[2];
    const float* W1   = (const float*)d_in[5];
    const float* b1   = (const float*)d_in[6];
    const float* W2   = (const float*)d_in[7];
    const float* b2   = (const float*)d_in[8];
    float* out = (float*)d_out;

    const int E = in_sizes[0] / NF;

    prep_weights<<<(384 * 256 + 256 * 128 + 255) / 256, 256>>>(W1, W2);

    cudaFuncSetAttribute(edge_mlp_h4,
                         cudaFuncAttributeMaxDynamicSharedMemorySize, SMEM_BYTES);
    const int grid = (E + BM - 1) / BM;
    edge_mlp_h4<<<grid, NTH, SMEM_BYTES>>>(src, dst, edge, b1, b2, out, E);
}